// round 9
// baseline (speedup 1.0000x reference)
#include <cuda_runtime.h>

// RNNModel: 2-layer tanh RNN, B=2048, T=512, I=5, H=64, O=1.
// R9: ALL weights in registers. Warp pair (p, p+4) owns 4 rows.
//  L1 warp: W_hh0 (128 regs) + W_ih1[:,0:32] (64 regs). Per step: layer-1
//   matvec -> publish h1[t] -> k-low partial of h1@W_ih1 -> store partial -> bar.
//  L2 warp: W_hh1 (128 regs) + W_ih1[:,32:64] (64 regs). Pre-bar: bias +
//   h2@W_hh1 (own regs). Post-bar: + k-high partial + L1's partial -> tanh.
//  Crossbar traffic is broadcasts + small stores only (no lane-distinct W LDS).
//  x read per step via broadcast __ldg (tiny, L1-resident).
// Grid: 128 CTAs x 256 thr (4 pairs); one named bar.sync(64)/period/warp.

#define BB 2048
#define TT 512

// smem float offsets (per pair stride noted)
#define OFF_H1  0        // per pair 512: h1[2][4][64]
#define OFF_H2  2048     // per pair 256: h2[4][64]
#define OFF_P   3072     // per pair 512: partial [4][32] ulonglong2
#define SMEM_FLOATS 5120
#define SMEM_BYTES (SMEM_FLOATS*4)

typedef unsigned long long ull;

__device__ __forceinline__ void fma2(ull &a, ull b, ull c){
    asm("fma.rn.f32x2 %0, %1, %2, %0;" : "+l"(a) : "l"(b), "l"(c));
}
__device__ __forceinline__ ull add2(ull a, ull b){
    ull r; asm("add.rn.f32x2 %0, %1, %2;" : "=l"(r) : "l"(a), "l"(b)); return r;
}
__device__ __forceinline__ ull pack2(float lo, float hi){
    ull r; asm("mov.b64 %0, {%1, %2};" : "=l"(r) : "f"(lo), "f"(hi)); return r;
}
__device__ __forceinline__ void unpk(ull a, float &lo, float &hi){
    asm("mov.b64 {%0, %1}, %2;" : "=f"(lo), "=f"(hi) : "l"(a));
}
__device__ __forceinline__ float fast_tanh(float x){
    float e;
    asm("ex2.approx.f32 %0, %1;" : "=f"(e) : "f"(x * 2.8853900817779268f));
    float r;
    asm("rcp.approx.f32 %0, %1;" : "=f"(r) : "f"(e + 1.0f));
    return fmaf(-2.0f, r, 1.0f);
}
__device__ __forceinline__ void barp(int id){
    asm volatile("bar.sync %0, 64;" :: "r"(id) : "memory");
}

__global__ void __launch_bounds__(256, 1) rnn_allreg_kernel(
    const float* __restrict__ x,
    const float* __restrict__ W_ih0, const float* __restrict__ W_hh0,
    const float* __restrict__ b_ih0, const float* __restrict__ b_hh0,
    const float* __restrict__ W_ih1, const float* __restrict__ W_hh1,
    const float* __restrict__ b_ih1, const float* __restrict__ b_hh1,
    const float* __restrict__ fc_W,  const float* __restrict__ fc_b,
    float* __restrict__ out)
{
    extern __shared__ float sm[];
    const int tid  = threadIdx.x;
    const int wid  = tid >> 5;
    const int ln   = tid & 31;
    const int pair = wid & 3;
    const int bid  = pair + 1;

    for (int idx = tid; idx < 3072; idx += 256) sm[idx] = 0.0f;   // h1 bufs + h2
    __syncthreads();

    const int r0  = blockIdx.x * 16 + pair * 4;
    float* h1b = sm + OFF_H1 + pair * 512;                  // [2][4][64]
    float* h2  = sm + OFF_H2 + pair * 256;                  // [4][64]
    ulonglong2* P = (ulonglong2*)(sm + OFF_P) + pair * 128; // [4][32]

    if (wid < 4){
        // ======== L1 warp: W_hh0 full + W_ih1 k=0..31 in regs ========
        ull Ra[32], Rb[32], Ia[16], Ib[16];
        {
            const ull* Wp = (const ull*)W_hh0;
            #pragma unroll
            for (int q = 0; q < 32; q++){
                Ra[q] = __ldg(Wp + ln*32 + q);
                Rb[q] = __ldg(Wp + (ln+32)*32 + q);
            }
            const ull* Ip = (const ull*)W_ih1;
            #pragma unroll
            for (int q = 0; q < 16; q++){
                Ia[q] = __ldg(Ip + ln*32 + q);
                Ib[q] = __ldg(Ip + (ln+32)*32 + q);
            }
        }
        float wa[5], wb[5];
        #pragma unroll
        for (int i = 0; i < 5; i++){
            wa[i] = W_ih0[ln*5 + i];
            wb[i] = W_ih0[(ln+32)*5 + i];
        }
        const float b0a = b_ih0[ln]    + b_hh0[ln];
        const float b0b = b_ih0[ln+32] + b_hh0[ln+32];

        for (int t = 0; t < TT; t++){
            const float* hsrc = h1b + ((t+1)&1)*256;   // h1[t-1]
            float*       hdst = h1b + (t&1)*256;       // h1[t]

            // x projection (broadcast LDG, independent of matvec)
            float sxa[4], sxb[4];
            #pragma unroll
            for (int r = 0; r < 4; r++){
                const float* xr = x + (size_t)(r0 + r) * (TT*5) + t*5;
                float x0 = __ldg(xr+0), x1 = __ldg(xr+1), x2 = __ldg(xr+2),
                      x3 = __ldg(xr+3), x4 = __ldg(xr+4);
                float sa = fmaf(x0, wa[0], b0a), sb = fmaf(x0, wb[0], b0b);
                sa = fmaf(x1, wa[1], sa); sb = fmaf(x1, wb[1], sb);
                sa = fmaf(x2, wa[2], sa); sb = fmaf(x2, wb[2], sb);
                sa = fmaf(x3, wa[3], sa); sb = fmaf(x3, wb[3], sb);
                sa = fmaf(x4, wa[4], sa); sb = fmaf(x4, wb[4], sb);
                sxa[r] = sa; sxb[r] = sb;
            }

            // layer-1 matvec: h1[t-1] @ W_hh0^T (regs)
            ull aA[4], aB[4];
            #pragma unroll
            for (int r = 0; r < 4; r++){ aA[r] = 0; aB[r] = 0; }
            #pragma unroll
            for (int q = 0; q < 16; q++){
                ulonglong2 c0 = *(const ulonglong2*)(hsrc +   0 + q*4);
                ulonglong2 c1 = *(const ulonglong2*)(hsrc +  64 + q*4);
                ulonglong2 c2 = *(const ulonglong2*)(hsrc + 128 + q*4);
                ulonglong2 c3 = *(const ulonglong2*)(hsrc + 192 + q*4);
                fma2(aA[0],Ra[2*q],c0.x); fma2(aB[0],Rb[2*q],c0.x); fma2(aA[0],Ra[2*q+1],c0.y); fma2(aB[0],Rb[2*q+1],c0.y);
                fma2(aA[1],Ra[2*q],c1.x); fma2(aB[1],Rb[2*q],c1.x); fma2(aA[1],Ra[2*q+1],c1.y); fma2(aB[1],Rb[2*q+1],c1.y);
                fma2(aA[2],Ra[2*q],c2.x); fma2(aB[2],Rb[2*q],c2.x); fma2(aA[2],Ra[2*q+1],c2.y); fma2(aB[2],Rb[2*q+1],c2.y);
                fma2(aA[3],Ra[2*q],c3.x); fma2(aB[3],Rb[2*q],c3.x); fma2(aA[3],Ra[2*q+1],c3.y); fma2(aB[3],Rb[2*q+1],c3.y);
            }
            #pragma unroll
            for (int r = 0; r < 4; r++){
                float lo, hi;
                unpk(aA[r], lo, hi); float u = fast_tanh(lo + hi + sxa[r]);
                unpk(aB[r], lo, hi); float v = fast_tanh(lo + hi + sxb[r]);
                hdst[r*64 + ln]      = u;
                hdst[r*64 + ln + 32] = v;
            }
            __syncwarp();   // h1[t] visible warp-wide

            // k-low partial of h1[t] @ W_ih1^T (regs), store to P
            #pragma unroll
            for (int r = 0; r < 4; r++){ aA[r] = 0; aB[r] = 0; }
            #pragma unroll
            for (int q = 0; q < 8; q++){
                ulonglong2 e0 = *(const ulonglong2*)(hdst +   0 + q*4);
                ulonglong2 e1 = *(const ulonglong2*)(hdst +  64 + q*4);
                ulonglong2 e2 = *(const ulonglong2*)(hdst + 128 + q*4);
                ulonglong2 e3 = *(const ulonglong2*)(hdst + 192 + q*4);
                fma2(aA[0],Ia[2*q],e0.x); fma2(aB[0],Ib[2*q],e0.x); fma2(aA[0],Ia[2*q+1],e0.y); fma2(aB[0],Ib[2*q+1],e0.y);
                fma2(aA[1],Ia[2*q],e1.x); fma2(aB[1],Ib[2*q],e1.x); fma2(aA[1],Ia[2*q+1],e1.y); fma2(aB[1],Ib[2*q+1],e1.y);
                fma2(aA[2],Ia[2*q],e2.x); fma2(aB[2],Ib[2*q],e2.x); fma2(aA[2],Ia[2*q+1],e2.y); fma2(aB[2],Ib[2*q+1],e2.y);
                fma2(aA[3],Ia[2*q],e3.x); fma2(aB[3],Ib[2*q],e3.x); fma2(aA[3],Ia[2*q+1],e3.y); fma2(aB[3],Ib[2*q+1],e3.y);
            }
            #pragma unroll
            for (int r = 0; r < 4; r++)
                P[r*32 + ln] = make_ulonglong2(aA[r], aB[r]);

            barp(bid);      // publish h1[t] + partial (bar drains STS)
        }
    } else {
        // ======== L2 warp: W_hh1 full + W_ih1 k=32..63 in regs ========
        ull Ra[32], Rb[32], Ia[16], Ib[16];
        {
            const ull* Wp = (const ull*)W_hh1;
            #pragma unroll
            for (int q = 0; q < 32; q++){
                Ra[q] = __ldg(Wp + ln*32 + q);
                Rb[q] = __ldg(Wp + (ln+32)*32 + q);
            }
            const ull* Ip = (const ull*)W_ih1;
            #pragma unroll
            for (int q = 0; q < 16; q++){
                Ia[q] = __ldg(Ip + ln*32 + 16 + q);
                Ib[q] = __ldg(Ip + (ln+32)*32 + 16 + q);
            }
        }
        const float b1a = b_ih1[ln]    + b_hh1[ln];
        const float b1b = b_ih1[ln+32] + b_hh1[ln+32];

        float ta[4], tb[4];
        #pragma unroll
        for (int r = 0; r < 4; r++){ ta[r] = 0.f; tb[r] = 0.f; }

        for (int t = 0; t < TT; t++){
            // ---- pre-barrier: bias + h2[t-1] @ W_hh1^T (regs; own smem) ----
            ull pA[4], pB[4];
            #pragma unroll
            for (int r = 0; r < 4; r++){ pA[r] = pack2(b1a, 0.f); pB[r] = pack2(b1b, 0.f); }
            #pragma unroll
            for (int q = 0; q < 16; q++){
                ulonglong2 g0 = *(const ulonglong2*)(h2 +   0 + q*4);
                ulonglong2 g1 = *(const ulonglong2*)(h2 +  64 + q*4);
                ulonglong2 g2 = *(const ulonglong2*)(h2 + 128 + q*4);
                ulonglong2 g3 = *(const ulonglong2*)(h2 + 192 + q*4);
                fma2(pA[0],Ra[2*q],g0.x); fma2(pB[0],Rb[2*q],g0.x); fma2(pA[0],Ra[2*q+1],g0.y); fma2(pB[0],Rb[2*q+1],g0.y);
                fma2(pA[1],Ra[2*q],g1.x); fma2(pB[1],Rb[2*q],g1.x); fma2(pA[1],Ra[2*q+1],g1.y); fma2(pB[1],Rb[2*q+1],g1.y);
                fma2(pA[2],Ra[2*q],g2.x); fma2(pB[2],Rb[2*q],g2.x); fma2(pA[2],Ra[2*q+1],g2.y); fma2(pB[2],Rb[2*q+1],g2.y);
                fma2(pA[3],Ra[2*q],g3.x); fma2(pB[3],Rb[2*q],g3.x); fma2(pA[3],Ra[2*q+1],g3.y); fma2(pB[3],Rb[2*q+1],g3.y);
            }

            barp(bid);      // h1[t] + L1 partial ready
            const float* hsrc = h1b + (t&1)*256;

            // ---- post-barrier: + h1[t][32:64] @ W_ih1^T (regs) + L1 partial ----
            #pragma unroll
            for (int q = 0; q < 8; q++){
                ulonglong2 e0 = *(const ulonglong2*)(hsrc +   0 + 32 + q*4);
                ulonglong2 e1 = *(const ulonglong2*)(hsrc +  64 + 32 + q*4);
                ulonglong2 e2 = *(const ulonglong2*)(hsrc + 128 + 32 + q*4);
                ulonglong2 e3 = *(const ulonglong2*)(hsrc + 192 + 32 + q*4);
                fma2(pA[0],Ia[2*q],e0.x); fma2(pB[0],Ib[2*q],e0.x); fma2(pA[0],Ia[2*q+1],e0.y); fma2(pB[0],Ib[2*q+1],e0.y);
                fma2(pA[1],Ia[2*q],e1.x); fma2(pB[1],Ib[2*q],e1.x); fma2(pA[1],Ia[2*q+1],e1.y); fma2(pB[1],Ib[2*q+1],e1.y);
                fma2(pA[2],Ia[2*q],e2.x); fma2(pB[2],Ib[2*q],e2.x); fma2(pA[2],Ia[2*q+1],e2.y); fma2(pB[2],Ib[2*q+1],e2.y);
                fma2(pA[3],Ia[2*q],e3.x); fma2(pB[3],Ib[2*q],e3.x); fma2(pA[3],Ia[2*q+1],e3.y); fma2(pB[3],Ib[2*q+1],e3.y);
            }
            #pragma unroll
            for (int r = 0; r < 4; r++){
                ulonglong2 p1 = P[r*32 + ln];
                ull sA = add2(pA[r], p1.x);
                ull sB = add2(pB[r], p1.y);
                float lo, hi;
                unpk(sA, lo, hi); ta[r] = fast_tanh(lo + hi);
                unpk(sB, lo, hi); tb[r] = fast_tanh(lo + hi);
            }
            #pragma unroll
            for (int r = 0; r < 4; r++){
                h2[r*64 + ln]      = ta[r];
                h2[r*64 + ln + 32] = tb[r];
            }
            __syncwarp();   // h2[t] visible for next pre-barrier phase
        }

        // ---- fc for this pair's 4 rows ----
        const float fa = fc_W[ln], fb = fc_W[ln+32];
        #pragma unroll
        for (int r = 0; r < 4; r++){
            float p = ta[r]*fa + tb[r]*fb;
            #pragma unroll
            for (int o = 16; o; o >>= 1)
                p += __shfl_xor_sync(0xffffffffu, p, o);
            if (ln == 0) out[r0 + r] = p + fc_b[0];
        }
    }
}

extern "C" void kernel_launch(void* const* d_in, const int* in_sizes, int n_in,
                              void* d_out, int out_size)
{
    const float* x     = (const float*)d_in[0];
    const float* W_ih0 = (const float*)d_in[1];
    const float* W_hh0 = (const float*)d_in[2];
    const float* b_ih0 = (const float*)d_in[3];
    const float* b_hh0 = (const float*)d_in[4];
    const float* W_ih1 = (const float*)d_in[5];
    const float* W_hh1 = (const float*)d_in[6];
    const float* b_ih1 = (const float*)d_in[7];
    const float* b_hh1 = (const float*)d_in[8];
    const float* fc_W  = (const float*)d_in[9];
    const float* fc_b  = (const float*)d_in[10];
    float* out = (float*)d_out;

    rnn_allreg_kernel<<<BB / 16, 256, SMEM_BYTES>>>(
        x, W_ih0, W_hh0, b_ih0, b_hh0, W_ih1, W_hh1, b_ih1, b_hh1, fc_W, fc_b, out);
}

// round 10
// speedup vs baseline: 1.1275x; 1.1275x over previous
#include <cuda_runtime.h>

// RNNModel: 2-layer tanh RNN, B=2048, T=512, I=5, H=64, O=1.
// R10: R8 warp-pair champion + stall trim toward the FFMA2 register-bank
// floor (~2304 cyc/SMSP/step):
//  - x via __ldg with one-step register prefetch (smem staging removed)
//  - depth-1 software pipelining of all smem h/W loads in the matvec loops
//  - W_ih1 split reverted (R9 regs=255 spill)
// Grid: 128 CTAs x 256 thr (4 pairs); 2 warps/SMSP; one bar.sync(64)/period.

#define BB 2048
#define TT 512

// shared float offsets
#define OFF_W1I 0        // W_ih1 [k2][ln] float4 = (W[l][2k2],W[l][2k2+1],W[l+32][2k2],W[l+32][2k2+1])
#define OFF_H1  4096     // per pair 512: h1[2][4][64]
#define OFF_H2  6144     // per pair 256: h2[4][64]
#define SMEM_FLOATS 7168
#define SMEM_BYTES (SMEM_FLOATS*4)

typedef unsigned long long ull;

__device__ __forceinline__ void fma2(ull &a, ull b, ull c){
    asm("fma.rn.f32x2 %0, %1, %2, %0;" : "+l"(a) : "l"(b), "l"(c));
}
__device__ __forceinline__ ull pack2(float lo, float hi){
    ull r; asm("mov.b64 %0, {%1, %2};" : "=l"(r) : "f"(lo), "f"(hi)); return r;
}
__device__ __forceinline__ void unpk(ull a, float &lo, float &hi){
    asm("mov.b64 {%0, %1}, %2;" : "=f"(lo), "=f"(hi) : "l"(a));
}
__device__ __forceinline__ float fast_tanh(float x){
    float e;
    asm("ex2.approx.f32 %0, %1;" : "=f"(e) : "f"(x * 2.8853900817779268f));
    float r;
    asm("rcp.approx.f32 %0, %1;" : "=f"(r) : "f"(e + 1.0f));
    return fmaf(-2.0f, r, 1.0f);
}
__device__ __forceinline__ void barp(int id){
    asm volatile("bar.sync %0, 64;" :: "r"(id) : "memory");
}

__global__ void __launch_bounds__(256, 1) rnn_r10_kernel(
    const float* __restrict__ x,
    const float* __restrict__ W_ih0, const float* __restrict__ W_hh0,
    const float* __restrict__ b_ih0, const float* __restrict__ b_hh0,
    const float* __restrict__ W_ih1, const float* __restrict__ W_hh1,
    const float* __restrict__ b_ih1, const float* __restrict__ b_hh1,
    const float* __restrict__ fc_W,  const float* __restrict__ fc_b,
    float* __restrict__ out)
{
    extern __shared__ float sm[];
    const int tid  = threadIdx.x;
    const int wid  = tid >> 5;
    const int ln   = tid & 31;
    const int pair = wid & 3;
    const int bid  = pair + 1;

    for (int idx = tid; idx < 1024; idx += 256){
        int k2 = idx >> 5, l = idx & 31, k = k2 * 2;
        ((float4*)(sm + OFF_W1I))[idx] =
            make_float4(W_ih1[l*64+k], W_ih1[l*64+k+1], W_ih1[(l+32)*64+k], W_ih1[(l+32)*64+k+1]);
    }
    for (int idx = tid; idx < 3072; idx += 256) sm[OFF_H1 + idx] = 0.0f;
    __syncthreads();

    const int r0  = blockIdx.x * 16 + pair * 4;
    float* h1b = sm + OFF_H1 + pair * 512;   // [2][4][64]
    float* h2  = sm + OFF_H2 + pair * 256;   // [4][64]

    if (wid < 4){
        // ================= layer-1 warp =================
        ull Ra[32], Rb[32];                   // W_hh0 rows ln, ln+32
        {
            const ull* Wp = (const ull*)W_hh0;
            #pragma unroll
            for (int q = 0; q < 32; q++){
                Ra[q] = __ldg(Wp + ln*32 + q);
                Rb[q] = __ldg(Wp + (ln+32)*32 + q);
            }
        }
        float wa[5], wb[5];
        #pragma unroll
        for (int i = 0; i < 5; i++){
            wa[i] = W_ih0[ln*5 + i];
            wb[i] = W_ih0[(ln+32)*5 + i];
        }
        const float b0a = b_ih0[ln]    + b_hh0[ln];
        const float b0b = b_ih0[ln+32] + b_hh0[ln+32];

        // x prefetch for t=0 (broadcast __ldg; float4+float per row)
        float4 xq[4]; float xs[4];
        #pragma unroll
        for (int r = 0; r < 4; r++){
            const float* xr = x + (size_t)(r0 + r) * (TT*5);
            xq[r] = make_float4(__ldg(xr), __ldg(xr+1), __ldg(xr+2), __ldg(xr+3));
            xs[r] = __ldg(xr+4);
        }

        for (int t = 0; t < TT; t++){
            const float* hsrc = h1b + ((t+1)&1)*256;   // h1[t-1]
            float*       hdst = h1b + (t&1)*256;       // h1[t]

            // consume prefetched x, then immediately issue t+1's loads
            float sxa[4], sxb[4];
            #pragma unroll
            for (int r = 0; r < 4; r++){
                float4 xv = xq[r]; float x4 = xs[r];
                float sa = fmaf(xv.x, wa[0], b0a), sb = fmaf(xv.x, wb[0], b0b);
                sa = fmaf(xv.y, wa[1], sa); sb = fmaf(xv.y, wb[1], sb);
                sa = fmaf(xv.z, wa[2], sa); sb = fmaf(xv.z, wb[2], sb);
                sa = fmaf(xv.w, wa[3], sa); sb = fmaf(xv.w, wb[3], sb);
                sa = fmaf(x4,   wa[4], sa); sb = fmaf(x4,   wb[4], sb);
                sxa[r] = sa; sxb[r] = sb;
            }
            if (t + 1 < TT){
                #pragma unroll
                for (int r = 0; r < 4; r++){
                    const float* xr = x + (size_t)(r0 + r) * (TT*5) + (t+1)*5;
                    xq[r] = make_float4(__ldg(xr), __ldg(xr+1), __ldg(xr+2), __ldg(xr+3));
                    xs[r] = __ldg(xr+4);
                }
            }

            // h1[t-1] @ W_hh0^T (W in regs, h pipelined depth-1)
            ull aA[4], aB[4];
            #pragma unroll
            for (int r = 0; r < 4; r++){ aA[r] = 0; aB[r] = 0; }
            {
                ulonglong2 c0 = *(const ulonglong2*)(hsrc +   0);
                ulonglong2 c1 = *(const ulonglong2*)(hsrc +  64);
                ulonglong2 c2 = *(const ulonglong2*)(hsrc + 128);
                ulonglong2 c3 = *(const ulonglong2*)(hsrc + 192);
                #pragma unroll
                for (int q = 0; q < 16; q++){
                    const int kn = (q < 15) ? q + 1 : 15;
                    ulonglong2 n0 = *(const ulonglong2*)(hsrc +   0 + kn*4);
                    ulonglong2 n1 = *(const ulonglong2*)(hsrc +  64 + kn*4);
                    ulonglong2 n2 = *(const ulonglong2*)(hsrc + 128 + kn*4);
                    ulonglong2 n3 = *(const ulonglong2*)(hsrc + 192 + kn*4);
                    fma2(aA[0],Ra[2*q],c0.x); fma2(aB[0],Rb[2*q],c0.x); fma2(aA[0],Ra[2*q+1],c0.y); fma2(aB[0],Rb[2*q+1],c0.y);
                    fma2(aA[1],Ra[2*q],c1.x); fma2(aB[1],Rb[2*q],c1.x); fma2(aA[1],Ra[2*q+1],c1.y); fma2(aB[1],Rb[2*q+1],c1.y);
                    fma2(aA[2],Ra[2*q],c2.x); fma2(aB[2],Rb[2*q],c2.x); fma2(aA[2],Ra[2*q+1],c2.y); fma2(aB[2],Rb[2*q+1],c2.y);
                    fma2(aA[3],Ra[2*q],c3.x); fma2(aB[3],Rb[2*q],c3.x); fma2(aA[3],Ra[2*q+1],c3.y); fma2(aB[3],Rb[2*q+1],c3.y);
                    c0 = n0; c1 = n1; c2 = n2; c3 = n3;
                }
            }
            #pragma unroll
            for (int r = 0; r < 4; r++){
                float lo, hi;
                unpk(aA[r], lo, hi); float u = fast_tanh(lo + hi + sxa[r]);
                unpk(aB[r], lo, hi); float v = fast_tanh(lo + hi + sxb[r]);
                hdst[r*64 + ln]      = u;
                hdst[r*64 + ln + 32] = v;
            }
            barp(bid);                        // h1[t] published (drains STS)
        }
    } else {
        // ================= layer-2 warp =================
        ull Ra[32], Rb[32];                   // W_hh1 rows ln, ln+32
        {
            const ull* Wp = (const ull*)W_hh1;
            #pragma unroll
            for (int q = 0; q < 32; q++){
                Ra[q] = __ldg(Wp + ln*32 + q);
                Rb[q] = __ldg(Wp + (ln+32)*32 + q);
            }
        }
        const float b1a = b_ih1[ln]    + b_hh1[ln];
        const float b1b = b_ih1[ln+32] + b_hh1[ln+32];
        const ulonglong2* WIp = (const ulonglong2*)(sm + OFF_W1I) + ln;

        float ta[4], tb[4];
        #pragma unroll
        for (int r = 0; r < 4; r++){ ta[r] = 0.f; tb[r] = 0.f; }

        for (int t = 0; t < TT; t++){
            // ---- pre-barrier: bias + h2[t-1] @ W_hh1^T (regs, h2 pipelined) ----
            ull pA[4], pB[4];
            #pragma unroll
            for (int r = 0; r < 4; r++){ pA[r] = pack2(b1a, 0.f); pB[r] = pack2(b1b, 0.f); }
            {
                ulonglong2 g0 = *(const ulonglong2*)(h2 +   0);
                ulonglong2 g1 = *(const ulonglong2*)(h2 +  64);
                ulonglong2 g2 = *(const ulonglong2*)(h2 + 128);
                ulonglong2 g3 = *(const ulonglong2*)(h2 + 192);
                #pragma unroll
                for (int q = 0; q < 16; q++){
                    const int kn = (q < 15) ? q + 1 : 15;
                    ulonglong2 n0 = *(const ulonglong2*)(h2 +   0 + kn*4);
                    ulonglong2 n1 = *(const ulonglong2*)(h2 +  64 + kn*4);
                    ulonglong2 n2 = *(const ulonglong2*)(h2 + 128 + kn*4);
                    ulonglong2 n3 = *(const ulonglong2*)(h2 + 192 + kn*4);
                    fma2(pA[0],Ra[2*q],g0.x); fma2(pB[0],Rb[2*q],g0.x); fma2(pA[0],Ra[2*q+1],g0.y); fma2(pB[0],Rb[2*q+1],g0.y);
                    fma2(pA[1],Ra[2*q],g1.x); fma2(pB[1],Rb[2*q],g1.x); fma2(pA[1],Ra[2*q+1],g1.y); fma2(pB[1],Rb[2*q+1],g1.y);
                    fma2(pA[2],Ra[2*q],g2.x); fma2(pB[2],Rb[2*q],g2.x); fma2(pA[2],Ra[2*q+1],g2.y); fma2(pB[2],Rb[2*q+1],g2.y);
                    fma2(pA[3],Ra[2*q],g3.x); fma2(pB[3],Rb[2*q],g3.x); fma2(pA[3],Ra[2*q+1],g3.y); fma2(pB[3],Rb[2*q+1],g3.y);
                    g0 = n0; g1 = n1; g2 = n2; g3 = n3;
                }
            }

            barp(bid);                        // h1[t] ready
            const float* hsrc = h1b + (t&1)*256;

            // ---- post-barrier: + h1[t] @ W_ih1^T (smem W + h, both pipelined) ----
            {
                ulonglong2 w0 = WIp[0], w1 = WIp[32];
                ulonglong2 e0 = *(const ulonglong2*)(hsrc +   0);
                ulonglong2 e1 = *(const ulonglong2*)(hsrc +  64);
                ulonglong2 e2 = *(const ulonglong2*)(hsrc + 128);
                ulonglong2 e3 = *(const ulonglong2*)(hsrc + 192);
                #pragma unroll
                for (int q = 0; q < 16; q++){
                    const int kn = (q < 15) ? q + 1 : 15;
                    ulonglong2 m0 = WIp[(2*kn  )*32];
                    ulonglong2 m1 = WIp[(2*kn+1)*32];
                    ulonglong2 f0 = *(const ulonglong2*)(hsrc +   0 + kn*4);
                    ulonglong2 f1 = *(const ulonglong2*)(hsrc +  64 + kn*4);
                    ulonglong2 f2 = *(const ulonglong2*)(hsrc + 128 + kn*4);
                    ulonglong2 f3 = *(const ulonglong2*)(hsrc + 192 + kn*4);
                    fma2(pA[0],w0.x,e0.x); fma2(pB[0],w0.y,e0.x); fma2(pA[0],w1.x,e0.y); fma2(pB[0],w1.y,e0.y);
                    fma2(pA[1],w0.x,e1.x); fma2(pB[1],w0.y,e1.x); fma2(pA[1],w1.x,e1.y); fma2(pB[1],w1.y,e1.y);
                    fma2(pA[2],w0.x,e2.x); fma2(pB[2],w0.y,e2.x); fma2(pA[2],w1.x,e2.y); fma2(pB[2],w1.y,e2.y);
                    fma2(pA[3],w0.x,e3.x); fma2(pB[3],w0.y,e3.x); fma2(pA[3],w1.x,e3.y); fma2(pB[3],w1.y,e3.y);
                    w0 = m0; w1 = m1;
                    e0 = f0; e1 = f1; e2 = f2; e3 = f3;
                }
            }
            #pragma unroll
            for (int r = 0; r < 4; r++){
                float lo, hi;
                unpk(pA[r], lo, hi); ta[r] = fast_tanh(lo + hi);
                unpk(pB[r], lo, hi); tb[r] = fast_tanh(lo + hi);
            }
            #pragma unroll
            for (int r = 0; r < 4; r++){
                h2[r*64 + ln]      = ta[r];
                h2[r*64 + ln + 32] = tb[r];
            }
            __syncwarp();                     // h2[t] visible for next pre-barrier phase
        }

        // ---- fc for this pair's 4 rows ----
        const float fa = fc_W[ln], fb = fc_W[ln+32];
        #pragma unroll
        for (int r = 0; r < 4; r++){
            float p = ta[r]*fa + tb[r]*fb;
            #pragma unroll
            for (int o = 16; o; o >>= 1)
                p += __shfl_xor_sync(0xffffffffu, p, o);
            if (ln == 0) out[r0 + r] = p + fc_b[0];
        }
    }
}

extern "C" void kernel_launch(void* const* d_in, const int* in_sizes, int n_in,
                              void* d_out, int out_size)
{
    const float* x     = (const float*)d_in[0];
    const float* W_ih0 = (const float*)d_in[1];
    const float* W_hh0 = (const float*)d_in[2];
    const float* b_ih0 = (const float*)d_in[3];
    const float* b_hh0 = (const float*)d_in[4];
    const float* W_ih1 = (const float*)d_in[5];
    const float* W_hh1 = (const float*)d_in[6];
    const float* b_ih1 = (const float*)d_in[7];
    const float* b_hh1 = (const float*)d_in[8];
    const float* fc_W  = (const float*)d_in[9];
    const float* fc_b  = (const float*)d_in[10];
    float* out = (float*)d_out;

    rnn_r10_kernel<<<BB / 16, 256, SMEM_BYTES>>>(
        x, W_ih0, W_hh0, b_ih0, b_hh0, W_ih1, W_hh1, b_ih1, b_hh1, fc_W, fc_b, out);
}